// round 16
// baseline (speedup 1.0000x reference)
#include <cuda_runtime.h>
#include <cstdint>

// VectorQuantize via legacy mma.sync TF32 (single pass) + candidate bitmask
// + exact fp32 rescore. R16 fixes R15's diagnosed limiter (issue-bound on
// xor-swizzle address math, duplicated across 2 passes):
//  - cbt stride 520 (520%32==8 -> banks 8*tig+g all distinct): B-fragment
//    loads are [thread_base + const_imm + blk*32B], ~1 IADD/blk.
//  - ONE MMA pass; per-slot 64-bit blk mask of candidates vs running min;
//    flagged blks exactly rescored (canonical chain). Exact argmin provably
//    flagged: approx(c*) <= gmin+eps <= runmin+2eps <= runmin+TAU.
//
// Exact chains (validated R1..R15, rel_err==0.0): dist = fl(fl(zsq-2*dot)+csq);
// dot = single f32x2 chain over dp ascending then fl(x+y); z_sq 4-chain
// stride-4; c_sq sequential scalar; ties -> lowest k (jnp.argmin).
// MMA fragment/result mapping identical to R14/R15 (empirically validated).

#define VQ_K   512
#define VQ_D   64
#define VQ_TPB 256
#define VQ_MT  256
#define VQ_TAU 2e-3f
#define VQ_CS  520      // cbt d-row stride in u32 (bank-spread, additive)

typedef unsigned long long ull;

// smem byte offsets
#define SM_CBT 0                         // 64*520 u32 = 133120
#define SM_ZE  133120                    // 256*68 f32 = 69632
#define SM_CSQ 202752                    // 512 f
#define SM_ZSQ 204800                    // 256 f
#define SM_WK  205824                    // 256 i
#define SM_TOTAL 206848

__device__ __forceinline__ ull vq_fma2(ull a, ull b, ull c) {
    ull d;
    asm("fma.rn.f32x2 %0, %1, %2, %3;" : "=l"(d) : "l"(a), "l"(b), "l"(c));
    return d;
}
__device__ __forceinline__ ull vq_add2(ull a, ull b) {
    ull d;
    asm("add.rn.f32x2 %0, %1, %2;" : "=l"(d) : "l"(a), "l"(b));
    return d;
}
__device__ __forceinline__ float2 vq_unpack(ull a) {
    float2 f;
    asm("mov.b64 {%0, %1}, %2;" : "=f"(f.x), "=f"(f.y) : "l"(a));
    return f;
}
__device__ __forceinline__ uint32_t f2tf32(float f) {
    uint32_t u;
    asm("cvt.rna.tf32.f32 %0, %1;" : "=r"(u) : "f"(f));
    return u;
}
__device__ __forceinline__ void mma_tf32(float& d0, float& d1, float& d2, float& d3,
                                         uint32_t a0, uint32_t a1, uint32_t a2,
                                         uint32_t a3, uint32_t b0, uint32_t b1) {
    asm volatile(
        "mma.sync.aligned.m16n8k8.row.col.f32.tf32.tf32.f32 "
        "{%0,%1,%2,%3}, {%4,%5,%6,%7}, {%8,%9}, {%0,%1,%2,%3};"
        : "+f"(d0), "+f"(d1), "+f"(d2), "+f"(d3)
        : "r"(a0), "r"(a1), "r"(a2), "r"(a3), "r"(b0), "r"(b1));
}

// exact canonical distance (z from smem, c from global cb via L2)
__device__ __forceinline__ float vq_exact(const float* zE, const ull* cbu,
                                          const float* s_csq, int row, int kc,
                                          float zq) {
    ull acc = 0;
    const ull* zp = (const ull*)(zE + row * 68);
    const ull* cp = cbu + kc * 32;
    #pragma unroll
    for (int dp = 0; dp < 32; ++dp) acc = vq_fma2(zp[dp], cp[dp], acc);
    float2 f = vq_unpack(acc);
    float dot = __fadd_rn(f.x, f.y);
    float t = __fsub_rn(zq, __fmul_rn(2.0f, dot));
    return __fadd_rn(t, s_csq[kc]);
}

__global__ void __launch_bounds__(VQ_TPB, 1)
vq_kernel(const float* __restrict__ z, const float* __restrict__ cb,
          float* __restrict__ out, int B) {
    extern __shared__ char smc[];
    uint32_t* cbt   = (uint32_t*)(smc + SM_CBT);
    float*    zE    = (float*)(smc + SM_ZE);
    float*    s_csq = (float*)(smc + SM_CSQ);
    float*    s_zsq = (float*)(smc + SM_ZSQ);
    int*      s_wk  = (int*)(smc + SM_WK);

    const int tid = threadIdx.x;
    const long long base = (long long)blockIdx.x * VQ_MT;
    const int rows_in = (int)((B - base) < VQ_MT ? (B - base) : VQ_MT);
    const ull* cbu = (const ull*)cb;

    // ---- stage codebook -> tf32, cbt[d*520 + n] (global-coalesced reads) ----
    #pragma unroll 4
    for (int i = tid; i < VQ_K * VQ_D; i += VQ_TPB) {
        int d = i & 63, n = i >> 6;
        cbt[d * VQ_CS + n] = f2tf32(cb[i]);
    }
    // ---- stage z tile fp32, row-major stride 68 ----
    {
        const float4* z4 = (const float4*)z + base * 16;
        #pragma unroll 4
        for (int i = tid; i < VQ_MT * 16; i += VQ_TPB) {
            int row = i >> 4, dg = i & 15;
            float4 v = (row < rows_in) ? z4[i] : make_float4(0.f, 0.f, 0.f, 0.f);
            *(float4*)(zE + row * 68 + dg * 4) = v;
        }
    }
    __syncthreads();

    // ---- c_sq exact (canonical sequential chain) ----
    #pragma unroll
    for (int k = tid; k < VQ_K; k += VQ_TPB) {
        float s = 0.0f;
        #pragma unroll
        for (int dp = 0; dp < 32; ++dp) {
            float2 c = vq_unpack(cbu[k * 32 + dp]);
            s = __fmaf_rn(c.x, c.x, s);
            s = __fmaf_rn(c.y, c.y, s);
        }
        s_csq[k] = s;
    }
    // ---- z_sq exact (canonical 4-chain stride-4) ----
    {
        int r = tid;   // TPB == VQ_MT
        const ull* zp = (const ull*)(zE + r * 68);
        ull a0 = 0, a1 = 0, a2 = 0, a3 = 0;
        #pragma unroll
        for (int i = 0; i < 32; i += 4) {
            a0 = vq_fma2(zp[i + 0], zp[i + 0], a0);
            a1 = vq_fma2(zp[i + 1], zp[i + 1], a1);
            a2 = vq_fma2(zp[i + 2], zp[i + 2], a2);
            a3 = vq_fma2(zp[i + 3], zp[i + 3], a3);
        }
        float2 s = vq_unpack(vq_add2(vq_add2(a0, a1), vq_add2(a2, a3)));
        s_zsq[r] = __fadd_rn(s.x, s.y);
    }
    __syncthreads();

    // ---- MMA setup: warp w owns rows [w*32, w*32+32) as 2 m16 blocks ----
    const int wid = tid >> 5, lane = tid & 31;
    const int g = lane >> 2, tig = lane & 3;
    const int rbase = wid * 32;

    int rows[4];
    rows[0] = rbase + g;       rows[1] = rbase + g + 8;
    rows[2] = rbase + 16 + g;  rows[3] = rbase + 16 + g + 8;
    float zsqr[4];
    #pragma unroll
    for (int s = 0; s < 4; ++s) zsqr[s] = s_zsq[rows[s]];

    // A fragments (resident; mapping validated in R14/R15)
    uint32_t aF[2][8][4];
    #pragma unroll
    for (int rb = 0; rb < 2; ++rb) {
        const float* zr0 = zE + rows[2 * rb] * 68;
        const float* zr1 = zE + rows[2 * rb + 1] * 68;
        #pragma unroll
        for (int ks = 0; ks < 8; ++ks) {
            int d0 = ks * 8 + tig;
            aF[rb][ks][0] = f2tf32(zr0[d0]);
            aF[rb][ks][1] = f2tf32(zr1[d0]);
            aF[rb][ks][2] = f2tf32(zr0[d0 + 4]);
            aF[rb][ks][3] = f2tf32(zr1[d0 + 4]);
        }
    }

    // ---- single pass: approx dists, running min + candidate bitmask ----
    const uint32_t* pB = cbt + tig * VQ_CS + g;        // bank 8*tig+g
    const float2*   pC = (const float2*)s_csq + tig;

    float rmin[4];
    ull   cmask[4];
    #pragma unroll
    for (int s = 0; s < 4; ++s) { rmin[s] = __int_as_float(0x7f800000); cmask[s] = 0; }

    #pragma unroll 1
    for (int blk = 0; blk < 64; ++blk) {
        // B fragments: 16 conflict-free LDS.32 at [base + imm + blk*32B]
        uint32_t bf[8][2];
        #pragma unroll
        for (int ks = 0; ks < 8; ++ks) {
            bf[ks][0] = pB[(ks * 8) * VQ_CS + blk * 8];
            bf[ks][1] = pB[(ks * 8 + 4) * VQ_CS + blk * 8];
        }
        float2 cc = pC[blk * 4];

        float v[2][4];
        #pragma unroll
        for (int rb = 0; rb < 2; ++rb) {
            float D[4][4];
            #pragma unroll
            for (int gg = 0; gg < 4; ++gg)
                #pragma unroll
                for (int e = 0; e < 4; ++e) D[gg][e] = 0.f;
            #pragma unroll
            for (int ks = 0; ks < 8; ++ks) {
                const int gg = ks >> 1;
                mma_tf32(D[gg][0], D[gg][1], D[gg][2], D[gg][3],
                         aF[rb][ks][0], aF[rb][ks][1], aF[rb][ks][2],
                         aF[rb][ks][3], bf[ks][0], bf[ks][1]);
            }
            float d0 = (D[0][0] + D[1][0]) + (D[2][0] + D[3][0]);
            float d1 = (D[0][1] + D[1][1]) + (D[2][1] + D[3][1]);
            float d2 = (D[0][2] + D[1][2]) + (D[2][2] + D[3][2]);
            float d3 = (D[0][3] + D[1][3]) + (D[2][3] + D[3][3]);
            v[rb][0] = __fadd_rn(__fmaf_rn(d0, -2.f, zsqr[2 * rb]), cc.x);
            v[rb][1] = __fadd_rn(__fmaf_rn(d1, -2.f, zsqr[2 * rb]), cc.y);
            v[rb][2] = __fadd_rn(__fmaf_rn(d2, -2.f, zsqr[2 * rb + 1]), cc.x);
            v[rb][3] = __fadd_rn(__fmaf_rn(d3, -2.f, zsqr[2 * rb + 1]), cc.y);
        }

        #pragma unroll
        for (int s = 0; s < 4; ++s) {
            const int rb = s >> 1, hh = s & 1;
            float pm = fminf(v[rb][2 * hh], v[rb][2 * hh + 1]);
            bool cand = pm <= rmin[s] + VQ_TAU;
            cmask[s] |= ((ull)cand) << blk;
            rmin[s] = fminf(rmin[s], pm);
        }
    }

    // ---- exact rescore of flagged blocks ----
    float bd[4];
    int   bkk[4];
    #pragma unroll
    for (int s = 0; s < 4; ++s) { bd[s] = __int_as_float(0x7f800000); bkk[s] = 1 << 30; }

    #pragma unroll
    for (int s = 0; s < 4; ++s) {
        ull m = cmask[s];
        while (m) {
            int b = __ffsll((long long)m) - 1;
            m &= m - 1;
            int kc0 = b * 8 + 2 * tig;
            #pragma unroll
            for (int e = 0; e < 2; ++e) {
                int kc = kc0 + e;
                float de = vq_exact(zE, cbu, s_csq, rows[s], kc, zsqr[s]);
                bool p = (de < bd[s]) || (de == bd[s] && kc < bkk[s]);
                bd[s]  = p ? de : bd[s];
                bkk[s] = p ? kc : bkk[s];
            }
        }
    }

    // ---- quad lexicographic reduce, write winner per row ----
    #pragma unroll
    for (int s = 0; s < 4; ++s) {
        #pragma unroll
        for (int off = 1; off <= 2; off <<= 1) {
            float od = __shfl_xor_sync(0xffffffffu, bd[s], off);
            int   ok = __shfl_xor_sync(0xffffffffu, bkk[s], off);
            bool p = (od < bd[s]) || (od == bd[s] && ok < bkk[s]);
            bd[s]  = p ? od : bd[s];
            bkk[s] = p ? ok : bkk[s];
        }
        if (tig == 0) s_wk[rows[s]] = bkk[s];
    }
    __syncthreads();

    // ---- outputs ----
    {
        const float4* cb4 = (const float4*)cb;
        const float4* z4  = (const float4*)z + base * 16;
        float4* o1 = (float4*)out + base * 16;
        float4* o2 = (float4*)out + (long long)B * 16 + base * 16;
        #pragma unroll 4
        for (int c = tid; c < VQ_MT * 16; c += VQ_TPB) {
            int r = c >> 4, dg = c & 15;
            if (r >= rows_in) break;
            int kbest = s_wk[r];
            float4 qv = cb4[kbest * 16 + dg];
            float4 zv = z4[c];
            float4 w;
            w.x = __fadd_rn(zv.x, __fsub_rn(qv.x, zv.x));
            w.y = __fadd_rn(zv.y, __fsub_rn(qv.y, zv.y));
            w.z = __fadd_rn(zv.z, __fsub_rn(qv.z, zv.z));
            w.w = __fadd_rn(zv.w, __fsub_rn(qv.w, zv.w));
            o1[c] = w;
            o2[c] = qv;
        }
    }
}

extern "C" void kernel_launch(void* const* d_in, const int* in_sizes, int n_in,
                              void* d_out, int out_size) {
    const float* z  = (const float*)d_in[0];
    const float* cb = (const float*)d_in[1];
    int sz0 = in_sizes[0];
    int sz1 = (n_in > 1) ? in_sizes[1] : 0;
    if (sz0 < sz1) {   // codebook is the small input (K*D = 32768)
        const float* t = z; z = cb; cb = t;
        int ts = sz0; sz0 = sz1; sz1 = ts;
    }
    int B = sz0 / VQ_D;

    cudaFuncSetAttribute(vq_kernel, cudaFuncAttributeMaxDynamicSharedMemorySize,
                         SM_TOTAL);
    int grid = (B + VQ_MT - 1) / VQ_MT;
    vq_kernel<<<grid, VQ_TPB, SM_TOTAL>>>(z, cb, (float*)d_out, B);
}

// round 17
// speedup vs baseline: 2.3073x; 2.3073x over previous
#include <cuda_runtime.h>
#include <cstdint>

// VectorQuantize via legacy mma.sync TF32, two-pass + exact fp32 rescore.
// R17 = R15's two-pass / final-threshold structure (validated, rescore rate
// ~0.3/row) + R16's affine stride-520 addressing (validated conflict-free,
// kills the xor-swizzle address-math that made R15 issue-bound at 22K
// instr/warp). R16's running-min mask (4.7 blocks/slot -> L1 wall) removed.
//
// Exact chains (validated R1..R16, rel_err==0.0): dist = fl(fl(zsq-2*dot)+csq);
// dot = single f32x2 chain over dp ascending then fl(x+y); z_sq 4-chain
// stride-4; c_sq sequential scalar; ties -> lowest k (jnp.argmin).
// tf32 approx error <= ~1.5e-4 << TAU=2e-3 -> exact argmin provably in the
// candidate set; candidates rescored with the canonical exact chain.

#define VQ_K   512
#define VQ_D   64
#define VQ_TPB 256
#define VQ_MT  256
#define VQ_TAU 2e-3f
#define VQ_CS  520      // cbt d-row stride in u32 (banks 8*tig+g, additive)

typedef unsigned long long ull;

// smem byte offsets
#define SM_CBT 0                         // 64*520 u32 = 133120
#define SM_ZE  133120                    // 256*68 f32 = 69632
#define SM_CSQ 202752                    // 512 f
#define SM_ZSQ 204800                    // 256 f
#define SM_WK  205824                    // 256 i
#define SM_TOTAL 206848

__device__ __forceinline__ ull vq_fma2(ull a, ull b, ull c) {
    ull d;
    asm("fma.rn.f32x2 %0, %1, %2, %3;" : "=l"(d) : "l"(a), "l"(b), "l"(c));
    return d;
}
__device__ __forceinline__ ull vq_add2(ull a, ull b) {
    ull d;
    asm("add.rn.f32x2 %0, %1, %2;" : "=l"(d) : "l"(a), "l"(b));
    return d;
}
__device__ __forceinline__ float2 vq_unpack(ull a) {
    float2 f;
    asm("mov.b64 {%0, %1}, %2;" : "=f"(f.x), "=f"(f.y) : "l"(a));
    return f;
}
__device__ __forceinline__ uint32_t f2tf32(float f) {
    uint32_t u;
    asm("cvt.rna.tf32.f32 %0, %1;" : "=r"(u) : "f"(f));
    return u;
}
__device__ __forceinline__ void mma_tf32(float& d0, float& d1, float& d2, float& d3,
                                         uint32_t a0, uint32_t a1, uint32_t a2,
                                         uint32_t a3, uint32_t b0, uint32_t b1) {
    asm volatile(
        "mma.sync.aligned.m16n8k8.row.col.f32.tf32.tf32.f32 "
        "{%0,%1,%2,%3}, {%4,%5,%6,%7}, {%8,%9}, {%0,%1,%2,%3};"
        : "+f"(d0), "+f"(d1), "+f"(d2), "+f"(d3)
        : "r"(a0), "r"(a1), "r"(a2), "r"(a3), "r"(b0), "r"(b1));
}

// exact canonical distance (z from smem, c from global cb via L2)
__device__ __forceinline__ float vq_exact(const float* zE, const ull* cbu,
                                          const float* s_csq, int row, int kc,
                                          float zq) {
    ull acc = 0;
    const ull* zp = (const ull*)(zE + row * 68);
    const ull* cp = cbu + kc * 32;
    #pragma unroll
    for (int dp = 0; dp < 32; ++dp) acc = vq_fma2(zp[dp], cp[dp], acc);
    float2 f = vq_unpack(acc);
    float dot = __fadd_rn(f.x, f.y);
    float t = __fsub_rn(zq, __fmul_rn(2.0f, dot));
    return __fadd_rn(t, s_csq[kc]);
}

// approx distances for one code-block (both rb), affine addressing
__device__ __forceinline__ void vq_blk(const uint32_t aF[2][8][4],
                                       const uint32_t* pB, int blk,
                                       float2 cc, const float* zsqr,
                                       float v[2][4]) {
    uint32_t bf[8][2];
    #pragma unroll
    for (int ks = 0; ks < 8; ++ks) {
        bf[ks][0] = pB[(ks * 8) * VQ_CS + blk * 8];
        bf[ks][1] = pB[(ks * 8 + 4) * VQ_CS + blk * 8];
    }
    #pragma unroll
    for (int rb = 0; rb < 2; ++rb) {
        float D[4][4];
        #pragma unroll
        for (int gg = 0; gg < 4; ++gg)
            #pragma unroll
            for (int e = 0; e < 4; ++e) D[gg][e] = 0.f;
        #pragma unroll
        for (int ks = 0; ks < 8; ++ks) {
            const int gg = ks >> 1;
            mma_tf32(D[gg][0], D[gg][1], D[gg][2], D[gg][3],
                     aF[rb][ks][0], aF[rb][ks][1], aF[rb][ks][2],
                     aF[rb][ks][3], bf[ks][0], bf[ks][1]);
        }
        float d0 = (D[0][0] + D[1][0]) + (D[2][0] + D[3][0]);
        float d1 = (D[0][1] + D[1][1]) + (D[2][1] + D[3][1]);
        float d2 = (D[0][2] + D[1][2]) + (D[2][2] + D[3][2]);
        float d3 = (D[0][3] + D[1][3]) + (D[2][3] + D[3][3]);
        v[rb][0] = __fadd_rn(__fmaf_rn(d0, -2.f, zsqr[2 * rb]), cc.x);
        v[rb][1] = __fadd_rn(__fmaf_rn(d1, -2.f, zsqr[2 * rb]), cc.y);
        v[rb][2] = __fadd_rn(__fmaf_rn(d2, -2.f, zsqr[2 * rb + 1]), cc.x);
        v[rb][3] = __fadd_rn(__fmaf_rn(d3, -2.f, zsqr[2 * rb + 1]), cc.y);
    }
}

__global__ void __launch_bounds__(VQ_TPB, 1)
vq_kernel(const float* __restrict__ z, const float* __restrict__ cb,
          float* __restrict__ out, int B) {
    extern __shared__ char smc[];
    uint32_t* cbt   = (uint32_t*)(smc + SM_CBT);
    float*    zE    = (float*)(smc + SM_ZE);
    float*    s_csq = (float*)(smc + SM_CSQ);
    float*    s_zsq = (float*)(smc + SM_ZSQ);
    int*      s_wk  = (int*)(smc + SM_WK);

    const int tid = threadIdx.x;
    const long long base = (long long)blockIdx.x * VQ_MT;
    const int rows_in = (int)((B - base) < VQ_MT ? (B - base) : VQ_MT);
    const ull* cbu = (const ull*)cb;

    // ---- stage codebook -> tf32, cbt[d*520 + n] ----
    #pragma unroll 4
    for (int i = tid; i < VQ_K * VQ_D; i += VQ_TPB) {
        int d = i & 63, n = i >> 6;
        cbt[d * VQ_CS + n] = f2tf32(cb[i]);
    }
    // ---- stage z tile fp32, row-major stride 68 ----
    {
        const float4* z4 = (const float4*)z + base * 16;
        #pragma unroll 4
        for (int i = tid; i < VQ_MT * 16; i += VQ_TPB) {
            int row = i >> 4, dg = i & 15;
            float4 v = (row < rows_in) ? z4[i] : make_float4(0.f, 0.f, 0.f, 0.f);
            *(float4*)(zE + row * 68 + dg * 4) = v;
        }
    }
    __syncthreads();

    // ---- c_sq exact (canonical sequential chain) ----
    #pragma unroll
    for (int k = tid; k < VQ_K; k += VQ_TPB) {
        float s = 0.0f;
        #pragma unroll
        for (int dp = 0; dp < 32; ++dp) {
            float2 c = vq_unpack(cbu[k * 32 + dp]);
            s = __fmaf_rn(c.x, c.x, s);
            s = __fmaf_rn(c.y, c.y, s);
        }
        s_csq[k] = s;
    }
    // ---- z_sq exact (canonical 4-chain stride-4) ----
    {
        int r = tid;   // TPB == VQ_MT
        const ull* zp = (const ull*)(zE + r * 68);
        ull a0 = 0, a1 = 0, a2 = 0, a3 = 0;
        #pragma unroll
        for (int i = 0; i < 32; i += 4) {
            a0 = vq_fma2(zp[i + 0], zp[i + 0], a0);
            a1 = vq_fma2(zp[i + 1], zp[i + 1], a1);
            a2 = vq_fma2(zp[i + 2], zp[i + 2], a2);
            a3 = vq_fma2(zp[i + 3], zp[i + 3], a3);
        }
        float2 s = vq_unpack(vq_add2(vq_add2(a0, a1), vq_add2(a2, a3)));
        s_zsq[r] = __fadd_rn(s.x, s.y);
    }
    __syncthreads();

    // ---- MMA setup: warp w owns rows [w*32, w*32+32) as 2 m16 blocks ----
    const int wid = tid >> 5, lane = tid & 31;
    const int g = lane >> 2, tig = lane & 3;
    const int rbase = wid * 32;

    int rows[4];
    rows[0] = rbase + g;       rows[1] = rbase + g + 8;
    rows[2] = rbase + 16 + g;  rows[3] = rbase + 16 + g + 8;
    float zsqr[4];
    #pragma unroll
    for (int s = 0; s < 4; ++s) zsqr[s] = s_zsq[rows[s]];

    // A fragments (resident; mapping validated R14..R16)
    uint32_t aF[2][8][4];
    #pragma unroll
    for (int rb = 0; rb < 2; ++rb) {
        const float* zr0 = zE + rows[2 * rb] * 68;
        const float* zr1 = zE + rows[2 * rb + 1] * 68;
        #pragma unroll
        for (int ks = 0; ks < 8; ++ks) {
            int d0 = ks * 8 + tig;
            aF[rb][ks][0] = f2tf32(zr0[d0]);
            aF[rb][ks][1] = f2tf32(zr1[d0]);
            aF[rb][ks][2] = f2tf32(zr0[d0 + 4]);
            aF[rb][ks][3] = f2tf32(zr1[d0 + 4]);
        }
    }

    const uint32_t* pB = cbt + tig * VQ_CS + g;   // bank 8*tig+g, affine
    const float2*   pC = (const float2*)s_csq + tig;

    // ---- pass 1: approx per-row min ----
    float rmin[4];
    #pragma unroll
    for (int s = 0; s < 4; ++s) rmin[s] = __int_as_float(0x7f800000);

    #pragma unroll 1
    for (int blk = 0; blk < 64; ++blk) {
        float v[2][4];
        vq_blk(aF, pB, blk, pC[blk * 4], zsqr, v);
        #pragma unroll
        for (int rb = 0; rb < 2; ++rb) {
            rmin[2 * rb]     = fminf(rmin[2 * rb], fminf(v[rb][0], v[rb][1]));
            rmin[2 * rb + 1] = fminf(rmin[2 * rb + 1], fminf(v[rb][2], v[rb][3]));
        }
    }
    float thr[4];
    #pragma unroll
    for (int s = 0; s < 4; ++s) {
        float m = rmin[s];
        m = fminf(m, __shfl_xor_sync(0xffffffffu, m, 1));
        m = fminf(m, __shfl_xor_sync(0xffffffffu, m, 2));
        thr[s] = m + VQ_TAU;
    }

    // ---- pass 2: candidates within final threshold -> exact rescore ----
    float bd[4];
    int   bkk[4];
    #pragma unroll
    for (int s = 0; s < 4; ++s) { bd[s] = __int_as_float(0x7f800000); bkk[s] = 1 << 30; }

    #pragma unroll 1
    for (int blk = 0; blk < 64; ++blk) {
        float v[2][4];
        vq_blk(aF, pB, blk, pC[blk * 4], zsqr, v);
        const int k0 = (blk << 3) + 2 * tig;
        #pragma unroll
        for (int rb = 0; rb < 2; ++rb) {
            #pragma unroll
            for (int e = 0; e < 4; ++e) {
                const int s = 2 * rb + (e >> 1);
                if (v[rb][e] <= thr[s]) {
                    int kc = k0 + (e & 1);
                    float de = vq_exact(zE, cbu, s_csq, rows[s], kc, zsqr[s]);
                    bool p = (de < bd[s]) || (de == bd[s] && kc < bkk[s]);
                    bd[s]  = p ? de : bd[s];
                    bkk[s] = p ? kc : bkk[s];
                }
            }
        }
    }

    // ---- quad lexicographic reduce, write winner per row ----
    #pragma unroll
    for (int s = 0; s < 4; ++s) {
        #pragma unroll
        for (int off = 1; off <= 2; off <<= 1) {
            float od = __shfl_xor_sync(0xffffffffu, bd[s], off);
            int   ok = __shfl_xor_sync(0xffffffffu, bkk[s], off);
            bool p = (od < bd[s]) || (od == bd[s] && ok < bkk[s]);
            bd[s]  = p ? od : bd[s];
            bkk[s] = p ? ok : bkk[s];
        }
        if (tig == 0) s_wk[rows[s]] = bkk[s];
    }
    __syncthreads();

    // ---- outputs ----
    {
        const float4* cb4 = (const float4*)cb;
        const float4* z4  = (const float4*)z + base * 16;
        float4* o1 = (float4*)out + base * 16;
        float4* o2 = (float4*)out + (long long)B * 16 + base * 16;
        #pragma unroll 4
        for (int c = tid; c < VQ_MT * 16; c += VQ_TPB) {
            int r = c >> 4, dg = c & 15;
            if (r >= rows_in) break;
            int kbest = s_wk[r];
            float4 qv = cb4[kbest * 16 + dg];
            float4 zv = z4[c];
            float4 w;
            w.x = __fadd_rn(zv.x, __fsub_rn(qv.x, zv.x));
            w.y = __fadd_rn(zv.y, __fsub_rn(qv.y, zv.y));
            w.z = __fadd_rn(zv.z, __fsub_rn(qv.z, zv.z));
            w.w = __fadd_rn(zv.w, __fsub_rn(qv.w, zv.w));
            o1[c] = w;
            o2[c] = qv;
        }
    }
}

extern "C" void kernel_launch(void* const* d_in, const int* in_sizes, int n_in,
                              void* d_out, int out_size) {
    const float* z  = (const float*)d_in[0];
    const float* cb = (const float*)d_in[1];
    int sz0 = in_sizes[0];
    int sz1 = (n_in > 1) ? in_sizes[1] : 0;
    if (sz0 < sz1) {   // codebook is the small input (K*D = 32768)
        const float* t = z; z = cb; cb = t;
        int ts = sz0; sz0 = sz1; sz1 = ts;
    }
    int B = sz0 / VQ_D;

    cudaFuncSetAttribute(vq_kernel, cudaFuncAttributeMaxDynamicSharedMemorySize,
                         SM_TOTAL);
    int grid = (B + VQ_MT - 1) / VQ_MT;
    vq_kernel<<<grid, VQ_TPB, SM_TOTAL>>>(z, cb, (float*)d_out, B);
}